// round 11
// baseline (speedup 1.0000x reference)
#include <cuda_runtime.h>

#define T_BINS 151
#define TILE   32
#define PADW   132          // 128 + 4 floats pad: float4-aligned, bank step 4
#define NREP   8            // histogram replicas (bank-spread for ATOMS)

// Global accumulators: [0..150] pos hist, [151..301] neg hist, [302] pos count.
// Zero at module load; the LAST block of every launch re-zeroes them after
// computing the loss -> every replay starts from zero (capture-safe).
__device__ float        g_hist[2 * T_BINS + 1];
__device__ unsigned int g_done;

// Packed dual-fp32 FMA (sm_103a FFMA2; only reachable via PTX).
__device__ __forceinline__ void fma2(unsigned long long& d,
                                     unsigned long long a,
                                     unsigned long long b)
{
    asm("fma.rn.f32x2 %0, %1, %2, %3;" : "=l"(d) : "l"(a), "l"(b), "l"(d));
}

__device__ __forceinline__ float unpack_sum(unsigned long long x)
{
    float lo = __uint_as_float((unsigned int)x);
    float hi = __uint_as_float((unsigned int)(x >> 32));
    return lo + hi;
}

__global__ __launch_bounds__(256) void hist_loss_kernel(
    const float* __restrict__ feats, const int* __restrict__ cls,
    float* __restrict__ out, int N, int NT, int nblocks)
{
    extern __shared__ float sm[];
    float* As    = sm;                          // TILE x PADW
    float* Bs    = As + TILE * PADW;            // TILE x PADW
    float* rhist = Bs + TILE * PADW;            // 2*T_BINS*NREP (replicated)
    int*   clsA  = (int*)(rhist + 2 * T_BINS * NREP);  // TILE
    int*   clsB  = clsA + TILE;                 // TILE
    int*   sPos  = clsB + TILE;                 // 1

    // Per-bin tables. allow[] keeps the reference's bitwise edge test; c1/c2
    // fold the (continuous) weight arithmetic into one FMA per weight.
    __shared__ float c1t[T_BINS];   // (t_lo[j]+step)*inv_step
    __shared__ float c2t[T_BINS];   // (step - t_hi[j])*inv_step
    __shared__ int   allow[T_BINS];
    __shared__ unsigned int s_ticket;

    const int tid = threadIdx.x;
    const float step     = (float)(2.0 / 150.0);
    const float inv_step = __fdiv_rn(1.0f, step);

    // Decode linear block id -> upper-triangular tile (bi, bj), bi <= bj.
    int k = blockIdx.x, bi = 0;
    while (k >= NT - bi) { k -= NT - bi; ++bi; }
    const int bj = bi + k;
    const bool diag = (bi == bj);

    for (int i = tid; i < 2 * T_BINS * NREP; i += 256) rhist[i] = 0.0f;
    if (tid == 0) *sPos = 0;
    if (tid < TILE) {
        int gi = bi * TILE + tid;
        clsA[tid] = (gi < N) ? cls[gi] : -1;
        int gj = bj * TILE + tid;
        clsB[tid] = (gj < N) ? cls[gj] : -2;
    }
    if (tid < T_BINS) {
        float qf = (float)tid;
        float d  = __fsub_rn(__fmul_rn(qf, step), 1.0f);                 // t_lo
        float t1 = __fadd_rn(-1.0f, __fmul_rn(__fadd_rn(qf, 1.0f), step)); // t_hi
        c1t[tid]   = (d + step) * inv_step;
        c2t[tid]   = (step - t1) * inv_step;
        allow[tid] = (d == __fsub_rn(t1, step));
    }

    // Load both feature tiles (32 rows x 128 floats) as float4, coalesced.
    const float4* f4 = (const float4*)feats;
    for (int idx = tid; idx < TILE * 32; idx += 256) {
        int r = idx >> 5, c = idx & 31;
        int gi = bi * TILE + r;
        float4 va = (gi < N) ? f4[gi * 32 + c] : make_float4(0.f, 0.f, 0.f, 0.f);
        *(float4*)(As + r * PADW + c * 4) = va;
        int gj = bj * TILE + r;
        float4 vb = (gj < N) ? f4[gj * 32 + c] : make_float4(0.f, 0.f, 0.f, 0.f);
        *(float4*)(Bs + r * PADW + c * 4) = vb;
    }
    __syncthreads();

    // Warp-square mapping: warp (wr, wc) in 2x4; lanes as 8x4 inside.
    // Thread covers rows {r0, r0+8}, cols {c0, c0+4} -> warp region 16x16.
    // a-loads: 8 distinct rows x 16B = 128B conflict-free -> 1 wavefront.
    const int w    = tid >> 5;
    const int lane = tid & 31;
    const int r0 = ((w >> 2) << 4) + (lane >> 2);   // 0..31
    const int c0 = ((w & 3) << 3) + (lane & 3);     // 0..31

    unsigned long long acc[2][2];
#pragma unroll
    for (int u = 0; u < 2; ++u)
#pragma unroll
        for (int v = 0; v < 2; ++v) acc[u][v] = 0ull;

#pragma unroll 2
    for (int kk = 0; kk < 128; kk += 4) {
        ulonglong2 a0 = *(const ulonglong2*)(As + r0 * PADW + kk);
        ulonglong2 a1 = *(const ulonglong2*)(As + (r0 + 8) * PADW + kk);
        ulonglong2 b0 = *(const ulonglong2*)(Bs + c0 * PADW + kk);
        ulonglong2 b1 = *(const ulonglong2*)(Bs + (c0 + 4) * PADW + kk);
        fma2(acc[0][0], a0.x, b0.x); fma2(acc[0][0], a0.y, b0.y);
        fma2(acc[0][1], a0.x, b1.x); fma2(acc[0][1], a0.y, b1.y);
        fma2(acc[1][0], a1.x, b0.x); fma2(acc[1][0], a1.y, b0.y);
        fma2(acc[1][1], a1.x, b1.x); fma2(acc[1][1], a1.y, b1.y);
    }

    // ---- Binning (reference fp32 semantics; weights via 1-FMA tables) ----
    const int rep = tid & (NREP - 1);
    const int ca[2] = { clsA[r0], clsA[r0 + 8] };
    const int cb[2] = { clsB[c0], clsB[c0 + 4] };
    int localPos = 0;
#pragma unroll
    for (int u = 0; u < 2; ++u) {
#pragma unroll
        for (int v = 0; v < 2; ++v) {
            int ri = r0 + 8 * u, rj = c0 + 4 * v;
            if ((!diag || ri < rj) && (bj * TILE + rj) < N) {
                float s  = unpack_sum(acc[u][v]);
                float qf = floorf(fmaf(s, inv_step, inv_step));  // (s+1)/step
                int   j0 = (int)qf;
                int   ng = (ca[u] == cb[v]) ? 0 : 1;
                localPos += (ng == 0);
                if (j0 >= 0 && j0 < T_BINS) {
                    float wb = fmaf(-s, inv_step, c1t[j0]);
                    atomicAdd(&rhist[(j0 * 2 + ng) * NREP + rep], wb);
                    if (allow[j0] && j0 + 1 < T_BINS) {
                        float wa = fmaf(s, inv_step, c2t[j0]);
                        atomicAdd(&rhist[((j0 + 1) * 2 + ng) * NREP + rep], wa);
                    }
                }
            }
        }
    }
    if (localPos) atomicAdd(sPos, localPos);
    __syncthreads();

    // Merge replicas and flush into the global accumulator (L2 atomics).
    for (int i = tid; i < 2 * T_BINS; i += 256) {
        int bin = (i < T_BINS) ? i : (i - T_BINS);
        int ng  = (i < T_BINS) ? 0 : 1;
        const float* src = &rhist[(bin * 2 + ng) * NREP];
        float v = 0.f;
#pragma unroll
        for (int r = 0; r < NREP; ++r) v += src[r];
        if (v != 0.0f) atomicAdd(&g_hist[i], v);
    }
    if (tid == 0 && *sPos) atomicAdd(&g_hist[2 * T_BINS], (float)(*sPos));

    // ---- last-block-done finalize ----
    __threadfence();
    if (tid == 0) s_ticket = atomicInc(&g_done, 0xFFFFFFFFu);
    __syncthreads();
    if (s_ticket != (unsigned)(nblocks - 1)) return;
    __threadfence();

    float* hp  = rhist;             // reuse shared memory
    float* hn  = rhist + T_BINS;
    float* red = As;                // reuse tile A region (256 floats)
    __shared__ float s_inv_pos, s_inv_neg;

    float vp = 0.f, vn = 0.f;
    if (tid < T_BINS) {
        vp = __ldcg(&g_hist[tid]);
        vn = __ldcg(&g_hist[T_BINS + tid]);
    }
    if (tid == 0) {
        float cnt  = __ldcg(&g_hist[2 * T_BINS]);
        float Ptot = 0.5f * (float)N * (float)(N - 1);
        s_inv_pos = 1.0f / cnt;
        s_inv_neg = 1.0f / (Ptot - cnt);
    }
    __syncthreads();
    if (tid < T_BINS) {
        hp[tid] = vp * s_inv_pos;
        hn[tid] = vn * s_inv_neg;
    }
    __syncthreads();

    // inclusive scan of hp (Hillis-Steele, 8 steps)
    for (int off = 1; off < T_BINS; off <<= 1) {
        float v = (tid < T_BINS && tid >= off) ? hp[tid - off] : 0.f;
        __syncthreads();
        if (tid < T_BINS) hp[tid] += v;
        __syncthreads();
    }

    // dot(hn, cdf) via power-of-2 tree reduce over 256 slots
    red[tid] = (tid < T_BINS) ? hn[tid] * hp[tid] : 0.f;
    __syncthreads();
#pragma unroll
    for (int s = 128; s > 0; s >>= 1) {
        if (tid < s) red[tid] += red[tid + s];
        __syncthreads();
    }
    if (tid == 0) out[0] = red[0];

    // Reset globals for the next replay (invariant: zero at kernel entry).
    for (int i = tid; i < 2 * T_BINS + 1; i += 256) g_hist[i] = 0.0f;
    if (tid == 0) g_done = 0u;
}

extern "C" void kernel_launch(void* const* d_in, const int* in_sizes, int n_in,
                              void* d_out, int out_size)
{
    const float* feats = (const float*)d_in[0];
    const int*   cls   = (const int*)d_in[1];
    int N  = in_sizes[1];                 // classes element count = number of rows
    int NT = (N + TILE - 1) / TILE;
    int nblocks = NT * (NT + 1) / 2;      // 528 for N=1024

    size_t smem = (size_t)(2 * TILE * PADW + 2 * T_BINS * NREP) * sizeof(float)
                + (size_t)(2 * TILE + 4) * sizeof(int);
    cudaFuncSetAttribute(hist_loss_kernel,
                         cudaFuncAttributeMaxDynamicSharedMemorySize, (int)smem);

    hist_loss_kernel<<<nblocks, 256, smem>>>(feats, cls, (float*)d_out,
                                             N, NT, nblocks);
}